// round 3
// baseline (speedup 1.0000x reference)
#include <cuda_runtime.h>
#include <cstdint>

#define N_NODES 100000
#define N_EDGES 1600000
#define D 128
#define NT ((N_NODES + 127) / 128)   /* 782 row tiles of 128 */

// ---------------- scratch (static device arrays; no allocations) -------------
__device__ int   g_off[N_NODES + 1];          // histogram -> exclusive offsets
__device__ int   g_cursor[N_NODES];           // scatter cursors
__device__ int   g_scol[N_EDGES];             // cols bucketed by destination row
__device__ float g_agg[(size_t)N_NODES * D];  // normalized neighborhood sums

// ---------------- k0: zero counters ------------------------------------------
__global__ void k_zero() {
    int i = blockIdx.x * blockDim.x + threadIdx.x;
    if (i <= N_NODES) g_off[i] = 0;
}

// ---------------- k1: histogram of destination rows --------------------------
// edge_index is int32 (JAX without x64 downcasts int64 -> int32).
__global__ void k_hist(const int* __restrict__ ei) {
    int e = blockIdx.x * blockDim.x + threadIdx.x;
    if (e < N_EDGES) atomicAdd(&g_off[ei[e]], 1);
}

// ---------------- k2: single-block exclusive scan (warp-shuffle based) -------
__global__ void k_scan() {
    __shared__ int warp_sums[32];
    __shared__ int s_carry;
    int tid = threadIdx.x, lane = tid & 31, wid = tid >> 5;
    if (tid == 0) s_carry = 0;
    __syncthreads();
    for (int base = 0; base < N_NODES; base += 1024) {
        int i = base + tid;
        int v = (i < N_NODES) ? g_off[i] : 0;
        int x = v;
        #pragma unroll
        for (int o = 1; o < 32; o <<= 1) {
            int t = __shfl_up_sync(0xffffffffu, x, o);
            if (lane >= o) x += t;
        }
        if (lane == 31) warp_sums[wid] = x;
        __syncthreads();
        if (wid == 0) {
            int w = warp_sums[lane];
            #pragma unroll
            for (int o = 1; o < 32; o <<= 1) {
                int t = __shfl_up_sync(0xffffffffu, w, o);
                if (lane >= o) w += t;
            }
            warp_sums[lane] = w;
        }
        __syncthreads();
        int carry = s_carry;
        int excl = carry + ((wid == 0) ? 0 : warp_sums[wid - 1]) + x - v;
        if (i < N_NODES) { g_off[i] = excl; g_cursor[i] = excl; }
        __syncthreads();
        if (tid == 0) s_carry = carry + warp_sums[31];
        __syncthreads();
    }
    if (tid == 0) g_off[N_NODES] = s_carry;
}

// ---------------- k3: bucket source cols by destination row ------------------
__global__ void k_scatter(const int* __restrict__ ei) {
    int e = blockIdx.x * blockDim.x + threadIdx.x;
    if (e < N_EDGES) {
        int r = ei[e];
        int c = ei[N_EDGES + e];
        int pos = atomicAdd(&g_cursor[r], 1);
        g_scol[pos] = c;
    }
}

// ---------------- k4: per-node gather-reduce + degree normalize --------------
// One warp per node, each lane owns a float4 column slice. Gather-only: no
// float atomics anywhere.
__global__ void k_agg(const float* __restrict__ x) {
    int gw = (blockIdx.x * blockDim.x + threadIdx.x) >> 5;
    int lane = threadIdx.x & 31;
    if (gw >= N_NODES) return;
    int s = g_off[gw], e = g_off[gw + 1];
    float4 a0 = make_float4(0.f, 0.f, 0.f, 0.f);
    float4 a1 = make_float4(0.f, 0.f, 0.f, 0.f);
    int j = s;
    for (; j + 1 < e; j += 2) {              // 2-way MLP
        int c0 = g_scol[j], c1 = g_scol[j + 1];
        float4 v0 = *(const float4*)(x + (size_t)c0 * D + lane * 4);
        float4 v1 = *(const float4*)(x + (size_t)c1 * D + lane * 4);
        a0.x += v0.x; a0.y += v0.y; a0.z += v0.z; a0.w += v0.w;
        a1.x += v1.x; a1.y += v1.y; a1.z += v1.z; a1.w += v1.w;
    }
    if (j < e) {
        int c0 = g_scol[j];
        float4 v0 = *(const float4*)(x + (size_t)c0 * D + lane * 4);
        a0.x += v0.x; a0.y += v0.y; a0.z += v0.z; a0.w += v0.w;
    }
    float inv = 1.0f / fmaxf((float)(e - s), 1.0f);
    float4 r;
    r.x = (a0.x + a1.x) * inv;
    r.y = (a0.y + a1.y) * inv;
    r.z = (a0.z + a1.z) * inv;
    r.w = (a0.w + a1.w) * inv;
    *(float4*)(g_agg + (size_t)gw * D + lane * 4) = r;
}

// ---------------- k5: fused GEMM  out = [agg | x] @ [W ; root] + bias --------
// Persistent CTAs; both weight matrices (128 KB) resident in SMEM; A tiles
// double buffered; TM=8 x TN=4 register tile; BM=128.
#define SMEM_B_ELEMS (256 * 128)
#define AS_STRIDE 132
#define AS_BUF (16 * AS_STRIDE)
#define SMEM_BYTES ((SMEM_B_ELEMS + 2 * AS_BUF) * 4)

__global__ void __launch_bounds__(512, 1) k_gemm(
    const float* __restrict__ x, const float* __restrict__ w,
    const float* __restrict__ root, const float* __restrict__ bias,
    float* __restrict__ out) {
    extern __shared__ float sm[];
    float* Bs = sm;                     // [256][128] : W rows 0..127, root 128..255
    float* As = sm + SMEM_B_ELEMS;      // [2][16][AS_STRIDE] transposed A tile

    int tid = threadIdx.x;
    for (int idx = tid; idx < SMEM_B_ELEMS; idx += 512)
        Bs[idx] = (idx < D * D) ? w[idx] : root[idx - D * D];

    const int n0 = (tid & 31) * 4;      // output col (lane -> 4 cols)
    const int m0 = (tid >> 5) * 8;      // output row group (warp -> 8 rows)
    const int lrow = tid >> 2;          // staging: row within tile (0..127)
    const int lk = (tid & 3) * 4;       // staging: k within chunk (0,4,8,12)
    float4 bias4 = *(const float4*)(bias + n0);
    __syncthreads();

    for (int tile = blockIdx.x; tile < NT; tile += gridDim.x) {
        int rb = tile * 128;
        {   // stage chunk 0 (k 0..15 of agg)
            int gr = rb + lrow;
            float4 v = make_float4(0.f, 0.f, 0.f, 0.f);
            if (gr < N_NODES) v = *(const float4*)(g_agg + (size_t)gr * D + lk);
            float* dst = As + lk * AS_STRIDE + lrow;
            dst[0] = v.x; dst[AS_STRIDE] = v.y;
            dst[2 * AS_STRIDE] = v.z; dst[3 * AS_STRIDE] = v.w;
        }
        __syncthreads();

        float4 acc[8];
        #pragma unroll
        for (int r = 0; r < 8; r++) acc[r] = make_float4(0.f, 0.f, 0.f, 0.f);

        #pragma unroll 1
        for (int kt = 0; kt < 16; kt++) {
            int buf = kt & 1;
            float4 pv = make_float4(0.f, 0.f, 0.f, 0.f);
            if (kt + 1 < 16) {          // prefetch next chunk from global
                int kcol = (kt + 1) * 16 + lk;
                int gr = rb + lrow;
                const float* src = (kcol < D)
                                       ? (g_agg + (size_t)gr * D + kcol)
                                       : (x + (size_t)gr * D + (kcol - D));
                if (gr < N_NODES) pv = *(const float4*)src;
            }
            const float* Bk = Bs + kt * 16 * D + n0;
            const float* Ak = As + buf * AS_BUF + m0;
            #pragma unroll
            for (int kk = 0; kk < 16; kk++) {
                float4 b  = *(const float4*)(Bk + kk * D);
                float4 a0 = *(const float4*)(Ak + kk * AS_STRIDE);
                float4 a1 = *(const float4*)(Ak + kk * AS_STRIDE + 4);
                acc[0].x += a0.x * b.x; acc[0].y += a0.x * b.y; acc[0].z += a0.x * b.z; acc[0].w += a0.x * b.w;
                acc[1].x += a0.y * b.x; acc[1].y += a0.y * b.y; acc[1].z += a0.y * b.z; acc[1].w += a0.y * b.w;
                acc[2].x += a0.z * b.x; acc[2].y += a0.z * b.y; acc[2].z += a0.z * b.z; acc[2].w += a0.z * b.w;
                acc[3].x += a0.w * b.x; acc[3].y += a0.w * b.y; acc[3].z += a0.w * b.z; acc[3].w += a0.w * b.w;
                acc[4].x += a1.x * b.x; acc[4].y += a1.x * b.y; acc[4].z += a1.x * b.z; acc[4].w += a1.x * b.w;
                acc[5].x += a1.y * b.x; acc[5].y += a1.y * b.y; acc[5].z += a1.y * b.z; acc[5].w += a1.y * b.w;
                acc[6].x += a1.z * b.x; acc[6].y += a1.z * b.y; acc[6].z += a1.z * b.z; acc[6].w += a1.z * b.w;
                acc[7].x += a1.w * b.x; acc[7].y += a1.w * b.y; acc[7].z += a1.w * b.z; acc[7].w += a1.w * b.w;
            }
            if (kt + 1 < 16) {
                __syncthreads();        // everyone done reading buf, prior writes done
                float* dst = As + (buf ^ 1) * AS_BUF + lk * AS_STRIDE + lrow;
                dst[0] = pv.x; dst[AS_STRIDE] = pv.y;
                dst[2 * AS_STRIDE] = pv.z; dst[3 * AS_STRIDE] = pv.w;
                __syncthreads();
            }
        }

        #pragma unroll
        for (int r = 0; r < 8; r++) {
            int gr = rb + m0 + r;
            if (gr < N_NODES) {
                float4 o;
                o.x = acc[r].x + bias4.x; o.y = acc[r].y + bias4.y;
                o.z = acc[r].z + bias4.z; o.w = acc[r].w + bias4.w;
                *(float4*)(out + (size_t)gr * D + n0) = o;
            }
        }
        // No barrier needed before next tile's stage: next stage writes buf 0,
        // whose last readers (kt==14) are already past the kt==14 barriers;
        // kt==15 readers use buf 1.
    }
}

// ---------------- launch ------------------------------------------------------
extern "C" void kernel_launch(void* const* d_in, const int* in_sizes, int n_in,
                              void* d_out, int out_size) {
    const float* x    = (const float*)d_in[0];
    const int*   ei   = (const int*)d_in[1];     // int32 edge_index [2, E]
    const float* w    = (const float*)d_in[2];
    const float* root = (const float*)d_in[3];
    const float* bias = (const float*)d_in[4];
    float* out = (float*)d_out;

    (void)in_sizes; (void)n_in; (void)out_size;

    cudaFuncSetAttribute(k_gemm, cudaFuncAttributeMaxDynamicSharedMemorySize,
                         SMEM_BYTES);

    k_zero<<<(N_NODES + 1 + 255) / 256, 256>>>();
    k_hist<<<(N_EDGES + 255) / 256, 256>>>(ei);
    k_scan<<<1, 1024>>>();
    k_scatter<<<(N_EDGES + 255) / 256, 256>>>(ei);
    k_agg<<<(N_NODES * 32 + 255) / 256, 256>>>(x);
    k_gemm<<<148, 512, SMEM_BYTES>>>(x, w, root, bias, out);
}

// round 6
// speedup vs baseline: 1.7599x; 1.7599x over previous
#include <cuda_runtime.h>
#include <cuda_bf16.h>
#include <cstdint>

#define N_NODES 100000
#define N_EDGES 1600000
#define D 128
#define NT64 ((N_NODES + 63) / 64)        /* 1563 tiles of 64 rows */
#define SCAN_NB ((N_NODES + 1023) / 1024) /* 98 */

// ---------------- scratch (static device arrays; no allocations) -------------
__device__ int   g_off[N_NODES + 1];
__device__ int   g_cursor[N_NODES];
__device__ int   g_part[SCAN_NB];
__device__ int   g_scol[N_EDGES];
__device__ float g_agg[(size_t)N_NODES * D];

// ======================= PTX helpers (baseline sm_100) =======================
__device__ __forceinline__ uint32_t smem_u32(const void* p) {
    uint32_t a;
    asm("{ .reg .u64 t; cvta.to.shared.u64 t, %1; cvt.u32.u64 %0, t; }"
        : "=r"(a) : "l"(p));
    return a;
}
// pack two floats to bf16x2: low 16 = bf16(lo), high 16 = bf16(hi)
__device__ __forceinline__ uint32_t packbf(float lo, float hi) {
    uint32_t r;
    asm("cvt.rn.bf16x2.f32 %0, %1, %2;" : "=r"(r) : "f"(hi), "f"(lo));
    return r;
}
#define LDSM_X4(r, addr)                                                          \
    asm volatile("ldmatrix.sync.aligned.m8n8.x4.shared.b16 {%0,%1,%2,%3}, [%4];" \
                 : "=r"((r)[0]), "=r"((r)[1]), "=r"((r)[2]), "=r"((r)[3])        \
                 : "r"(addr))
#define LDSM_X2(r, addr)                                                          \
    asm volatile("ldmatrix.sync.aligned.m8n8.x2.shared.b16 {%0,%1}, [%2];"       \
                 : "=r"((r)[0]), "=r"((r)[1])                                    \
                 : "r"(addr))
#define MMA_BF16(d, a, b)                                                         \
    asm volatile("mma.sync.aligned.m16n8k16.row.col.f32.bf16.bf16.f32 "          \
                 "{%0,%1,%2,%3}, {%4,%5,%6,%7}, {%8,%9}, {%0,%1,%2,%3};"         \
                 : "+f"((d)[0]), "+f"((d)[1]), "+f"((d)[2]), "+f"((d)[3])        \
                 : "r"((a)[0]), "r"((a)[1]), "r"((a)[2]), "r"((a)[3]),           \
                   "r"((b)[0]), "r"((b)[1]))

// ---------------- k0: zero counters ------------------------------------------
__global__ void k_zero() {
    int i = blockIdx.x * blockDim.x + threadIdx.x;
    if (i <= N_NODES) g_off[i] = 0;
}

// ---------------- k1: histogram of destination rows (edge_index is int32) ----
__global__ void k_hist(const int* __restrict__ ei) {
    int e = blockIdx.x * blockDim.x + threadIdx.x;
    if (e < N_EDGES) atomicAdd(&g_off[ei[e]], 1);
}

// ---------------- multi-block exclusive scan ---------------------------------
__global__ void k_scan_a() {
    __shared__ int ws[32];
    int tid = threadIdx.x, lane = tid & 31, wid = tid >> 5;
    int i = blockIdx.x * 1024 + tid;
    int v = (i < N_NODES) ? g_off[i] : 0;
    #pragma unroll
    for (int o = 16; o > 0; o >>= 1) v += __shfl_down_sync(0xffffffffu, v, o);
    if (lane == 0) ws[wid] = v;
    __syncthreads();
    if (wid == 0) {
        int t = ws[lane];
        #pragma unroll
        for (int o = 16; o > 0; o >>= 1) t += __shfl_down_sync(0xffffffffu, t, o);
        if (lane == 0) g_part[blockIdx.x] = t;
    }
}
__global__ void k_scan_b() {
    __shared__ int ws[4];
    int tid = threadIdx.x, lane = tid & 31, wid = tid >> 5;
    int v = (tid < SCAN_NB) ? g_part[tid] : 0;
    int xs = v;
    #pragma unroll
    for (int o = 1; o < 32; o <<= 1) {
        int t = __shfl_up_sync(0xffffffffu, xs, o);
        if (lane >= o) xs += t;
    }
    if (lane == 31) ws[wid] = xs;
    __syncthreads();
    if (tid == 0) {
        int a = 0;
        #pragma unroll
        for (int j = 0; j < 4; j++) { int t = ws[j]; ws[j] = a; a += t; }
        g_off[N_NODES] = a;
    }
    __syncthreads();
    int excl = ws[wid] + xs - v;
    if (tid < SCAN_NB) g_part[tid] = excl;
}
__global__ void k_scan_c() {
    __shared__ int ws[32];
    int tid = threadIdx.x, lane = tid & 31, wid = tid >> 5;
    int i = blockIdx.x * 1024 + tid;
    int v = (i < N_NODES) ? g_off[i] : 0;
    int xs = v;
    #pragma unroll
    for (int o = 1; o < 32; o <<= 1) {
        int t = __shfl_up_sync(0xffffffffu, xs, o);
        if (lane >= o) xs += t;
    }
    if (lane == 31) ws[wid] = xs;
    __syncthreads();
    if (wid == 0) {
        int t = ws[lane];
        #pragma unroll
        for (int o = 1; o < 32; o <<= 1) {
            int u = __shfl_up_sync(0xffffffffu, t, o);
            if (lane >= o) t += u;
        }
        ws[lane] = t;
    }
    __syncthreads();
    int excl = g_part[blockIdx.x] + ((wid == 0) ? 0 : ws[wid - 1]) + xs - v;
    if (i < N_NODES) { g_off[i] = excl; g_cursor[i] = excl; }
}

// ---------------- k3: bucket source cols by destination row ------------------
__global__ void k_scatter(const int* __restrict__ ei) {
    int e = blockIdx.x * blockDim.x + threadIdx.x;
    if (e < N_EDGES) {
        int r = ei[e];
        int c = ei[N_EDGES + e];
        int pos = atomicAdd(&g_cursor[r], 1);
        g_scol[pos] = c;
    }
}

// ---------------- k4: per-node gather-reduce + degree normalize --------------
__global__ void k_agg(const float* __restrict__ x) {
    int gw = (blockIdx.x * blockDim.x + threadIdx.x) >> 5;
    int lane = threadIdx.x & 31;
    if (gw >= N_NODES) return;
    int s = g_off[gw], e = g_off[gw + 1];
    float4 a0 = make_float4(0.f, 0.f, 0.f, 0.f);
    float4 a1 = make_float4(0.f, 0.f, 0.f, 0.f);
    int j = s;
    for (; j + 1 < e; j += 2) {
        int c0 = g_scol[j], c1 = g_scol[j + 1];
        float4 v0 = *(const float4*)(x + (size_t)c0 * D + lane * 4);
        float4 v1 = *(const float4*)(x + (size_t)c1 * D + lane * 4);
        a0.x += v0.x; a0.y += v0.y; a0.z += v0.z; a0.w += v0.w;
        a1.x += v1.x; a1.y += v1.y; a1.z += v1.z; a1.w += v1.w;
    }
    if (j < e) {
        int c0 = g_scol[j];
        float4 v0 = *(const float4*)(x + (size_t)c0 * D + lane * 4);
        a0.x += v0.x; a0.y += v0.y; a0.z += v0.z; a0.w += v0.w;
    }
    float inv = 1.0f / fmaxf((float)(e - s), 1.0f);
    float4 r;
    r.x = (a0.x + a1.x) * inv; r.y = (a0.y + a1.y) * inv;
    r.z = (a0.z + a1.z) * inv; r.w = (a0.w + a1.w) * inv;
    *(float4*)(g_agg + (size_t)gw * D + lane * 4) = r;
}

// ---------------- k5: mma.sync bf16 split GEMM  out = [agg|x]@[W;root]+bias --
// B stored [n][k] bf16 (hi/lo), stride 264 elems. A staged per 64-K chunk,
// [row][k] bf16 (hi/lo), stride 72 elems. 8 warps in 2(M)x4(N); each warp
// computes 32x32 of the 64x128 output tile via m16n8k16 HMMA.
#define BS_STRIDE 264
#define AS_STRIDE 72
#define SO_BIAS 0
#define SO_BHI  512
#define SO_BLO  (SO_BHI + 128 * BS_STRIDE * 2)          /* +67584 */
#define SO_AHI  (SO_BLO + 128 * BS_STRIDE * 2)
#define SO_ALO  (SO_AHI + 64 * AS_STRIDE * 2)           /* +9216 */
#define SMEM_GEMM (SO_ALO + 64 * AS_STRIDE * 2)

__global__ void __launch_bounds__(256, 1) k_gemm_mma(
    const float* __restrict__ x, const float* __restrict__ w,
    const float* __restrict__ root, const float* __restrict__ bias,
    float* __restrict__ out) {
    extern __shared__ char smem[];
    uint32_t sb = smem_u32(smem);
    float* sBias = (float*)(smem + SO_BIAS);
    int tid = threadIdx.x, lane = tid & 31, wid = tid >> 5;

    // ---- fill B hi/lo: Bs[n][k] = Bmat[k][n], Bmat = [W ; root] -------------
    for (int idx = tid; idx < 256 * 128; idx += 256) {
        int k = idx >> 7, n = idx & 127;
        float v = (k < 128) ? w[(k << 7) + n] : root[((k - 128) << 7) + n];
        __nv_bfloat16 h = __float2bfloat16(v);
        float rl = v - __bfloat162float(h);
        *(__nv_bfloat16*)(smem + SO_BHI + (n * BS_STRIDE + k) * 2) = h;
        *(__nv_bfloat16*)(smem + SO_BLO + (n * BS_STRIDE + k) * 2) =
            __float2bfloat16(rl);
    }
    if (tid < 128) sBias[tid] = bias[tid];
    __syncthreads();

    const int g = lane >> 2, tg = lane & 3;
    const int wm = wid >> 2, wn = wid & 3;       // 2 x 4 warp grid
    const int mbase_w = wm * 32, nbase_w = wn * 32;

    // ldmatrix source addresses (byte offsets into smem)
    const uint32_t aAddrBase =
        sb + SO_AHI + (uint32_t)(mbase_w + (lane & 15)) * (AS_STRIDE * 2) +
        (uint32_t)(lane >> 4) * 16;              // + mt*16 rows + k16*32 bytes
    const uint32_t bAddrBase =
        sb + SO_BHI + (uint32_t)(nbase_w + (lane & 7)) * (BS_STRIDE * 2) +
        (uint32_t)((lane >> 3) & 1) * 16;        // + nt*8 rows + k*2 bytes
    const uint32_t ALO_OFF = SO_ALO - SO_AHI;
    const uint32_t BLO_OFF = SO_BLO - SO_BHI;

    // staging indices: thread -> (row, 4-col group)
    const int srow = tid >> 2, sq = tid & 3;

    for (int tile = blockIdx.x; tile < NT64; tile += gridDim.x) {
        int rb = tile * 64;
        float acc[2][4][4];
        #pragma unroll
        for (int mt = 0; mt < 2; mt++)
            #pragma unroll
            for (int nt = 0; nt < 4; nt++)
                #pragma unroll
                for (int q = 0; q < 4; q++) acc[mt][nt][q] = 0.f;

        #pragma unroll 1
        for (int kc = 0; kc < 4; kc++) {
            // ---- stage A chunk: rows rb..rb+63, k cols kc*64..+63 ----------
            {
                int gr = rb + srow;
                bool valid = gr < N_NODES;
                const float* src = (kc < 2)
                    ? (g_agg + (size_t)gr * D + kc * 64)
                    : (x + (size_t)gr * D + (kc - 2) * 64);
                #pragma unroll
                for (int p = 0; p < 4; p++) {
                    int col = (sq + p * 4) * 4;          // 0..60, step 16
                    float4 v = valid ? *(const float4*)(src + col)
                                     : make_float4(0.f, 0.f, 0.f, 0.f);
                    uint32_t h0 = packbf(v.x, v.y);
                    uint32_t h1 = packbf(v.z, v.w);
                    float r0 = v.x - __uint_as_float(h0 << 16);
                    float r1 = v.y - __uint_as_float(h0 & 0xffff0000u);
                    float r2 = v.z - __uint_as_float(h1 << 16);
                    float r3 = v.w - __uint_as_float(h1 & 0xffff0000u);
                    uint32_t l0 = packbf(r0, r1);
                    uint32_t l1 = packbf(r2, r3);
                    char* base = smem + (srow * AS_STRIDE + col) * 2;
                    *(uint2*)(base + SO_AHI) = make_uint2(h0, h1);
                    *(uint2*)(base + SO_ALO) = make_uint2(l0, l1);
                }
            }
            __syncthreads();

            // ---- compute: 4 k16-steps over this 64-wide chunk --------------
            #pragma unroll
            for (int k16 = 0; k16 < 4; k16++) {
                uint32_t bh[4][2], bl[4][2];
                uint32_t bcol = (uint32_t)(kc * 64 + k16 * 16) * 2;
                #pragma unroll
                for (int nt = 0; nt < 4; nt++) {
                    uint32_t ba = bAddrBase + (uint32_t)nt * (8 * BS_STRIDE * 2) + bcol;
                    LDSM_X2(bh[nt], ba);
                    LDSM_X2(bl[nt], ba + BLO_OFF);
                }
                #pragma unroll
                for (int mt = 0; mt < 2; mt++) {
                    uint32_t ah[4], al[4];
                    uint32_t aa = aAddrBase + (uint32_t)mt * (16 * AS_STRIDE * 2) +
                                  (uint32_t)k16 * 32;
                    LDSM_X4(ah, aa);
                    LDSM_X4(al, aa + ALO_OFF);
                    #pragma unroll
                    for (int nt = 0; nt < 4; nt++) {
                        MMA_BF16(acc[mt][nt], ah, bh[nt]);
                        MMA_BF16(acc[mt][nt], ah, bl[nt]);
                        MMA_BF16(acc[mt][nt], al, bh[nt]);
                    }
                }
            }
            __syncthreads();   // done reading A chunk before next stage
        }

        // ---- epilogue: write 32x32 per warp with bias ----------------------
        #pragma unroll
        for (int mt = 0; mt < 2; mt++) {
            int r0 = rb + mbase_w + mt * 16 + g;
            #pragma unroll
            for (int nt = 0; nt < 4; nt++) {
                int col = nbase_w + nt * 8 + tg * 2;
                float b0 = sBias[col], b1 = sBias[col + 1];
                if (r0 < N_NODES)
                    *(float2*)(out + (size_t)r0 * D + col) =
                        make_float2(acc[mt][nt][0] + b0, acc[mt][nt][1] + b1);
                int r1 = r0 + 8;
                if (r1 < N_NODES)
                    *(float2*)(out + (size_t)r1 * D + col) =
                        make_float2(acc[mt][nt][2] + b0, acc[mt][nt][3] + b1);
            }
        }
    }
}

// ---------------- launch ------------------------------------------------------
extern "C" void kernel_launch(void* const* d_in, const int* in_sizes, int n_in,
                              void* d_out, int out_size) {
    const float* x    = (const float*)d_in[0];
    const int*   ei   = (const int*)d_in[1];     // int32 edge_index [2, E]
    const float* w    = (const float*)d_in[2];
    const float* root = (const float*)d_in[3];
    const float* bias = (const float*)d_in[4];
    float* out = (float*)d_out;

    (void)in_sizes; (void)n_in; (void)out_size;

    cudaFuncSetAttribute(k_gemm_mma, cudaFuncAttributeMaxDynamicSharedMemorySize,
                         SMEM_GEMM);

    k_zero<<<(N_NODES + 1 + 255) / 256, 256>>>();
    k_hist<<<(N_EDGES + 255) / 256, 256>>>(ei);
    k_scan_a<<<SCAN_NB, 1024>>>();
    k_scan_b<<<1, 128>>>();
    k_scan_c<<<SCAN_NB, 1024>>>();
    k_scatter<<<(N_EDGES + 255) / 256, 256>>>(ei);
    k_agg<<<(N_NODES * 32 + 255) / 256, 256>>>(x);
    k_gemm_mma<<<148, 256, SMEM_GEMM>>>(x, w, root, bias, out);
}

// round 8
// speedup vs baseline: 1.8300x; 1.0398x over previous
#include <cuda_runtime.h>
#include <cuda_bf16.h>
#include <cuda_fp16.h>
#include <cstdint>

#define N_NODES 100000
#define N_EDGES 1600000
#define D 128
#define NT64 ((N_NODES + 63) / 64)        /* 1563 tiles of 64 rows */
#define SCAN_NB ((N_NODES + 1023) / 1024) /* 98 */

// ---------------- scratch (static device arrays; no allocations) -------------
__device__ int    g_off[N_NODES + 1];
__device__ int    g_cursor[N_NODES];
__device__ int    g_part[SCAN_NB];
__device__ int    g_scol[N_EDGES];
__device__ float  g_agg[(size_t)N_NODES * D];
__device__ __half g_xh[(size_t)N_NODES * D];   // fp16 copy of x for gather
__device__ uint4  g_bimg[8480];                // prebuilt smem image: bias+Bhi+Blo

// ======================= PTX helpers (baseline sm_100) =======================
__device__ __forceinline__ uint32_t smem_u32(const void* p) {
    uint32_t a;
    asm("{ .reg .u64 t; cvta.to.shared.u64 t, %1; cvt.u32.u64 %0, t; }"
        : "=r"(a) : "l"(p));
    return a;
}
// pack two floats to bf16x2: low 16 = bf16(lo), high 16 = bf16(hi)
__device__ __forceinline__ uint32_t packbf(float lo, float hi) {
    uint32_t r;
    asm("cvt.rn.bf16x2.f32 %0, %1, %2;" : "=r"(r) : "f"(hi), "f"(lo));
    return r;
}
#define LDSM_X4(r, addr)                                                          \
    asm volatile("ldmatrix.sync.aligned.m8n8.x4.shared.b16 {%0,%1,%2,%3}, [%4];" \
                 : "=r"((r)[0]), "=r"((r)[1]), "=r"((r)[2]), "=r"((r)[3])        \
                 : "r"(addr))
#define LDSM_X2(r, addr)                                                          \
    asm volatile("ldmatrix.sync.aligned.m8n8.x2.shared.b16 {%0,%1}, [%2];"       \
                 : "=r"((r)[0]), "=r"((r)[1])                                    \
                 : "r"(addr))
#define MMA_BF16(d, a, b)                                                         \
    asm volatile("mma.sync.aligned.m16n8k16.row.col.f32.bf16.bf16.f32 "          \
                 "{%0,%1,%2,%3}, {%4,%5,%6,%7}, {%8,%9}, {%0,%1,%2,%3};"         \
                 : "+f"((d)[0]), "+f"((d)[1]), "+f"((d)[2]), "+f"((d)[3])        \
                 : "r"((a)[0]), "r"((a)[1]), "r"((a)[2]), "r"((a)[3]),           \
                   "r"((b)[0]), "r"((b)[1]))

// ---------------- k0: zero counters ------------------------------------------
__global__ void k_zero() {
    int i = blockIdx.x * blockDim.x + threadIdx.x;
    if (i <= N_NODES) g_off[i] = 0;
}

// ---------------- k_cvt: x -> fp16 copy for the gather path -------------------
__global__ void k_cvt(const float* __restrict__ x) {
    size_t i = (size_t)blockIdx.x * 256 + threadIdx.x;
    if (i < (size_t)N_NODES * 32) {
        float4 v = ((const float4*)x)[i];
        __half2 h0 = __floats2half2_rn(v.x, v.y);
        __half2 h1 = __floats2half2_rn(v.z, v.w);
        uint2 u;
        u.x = *reinterpret_cast<uint32_t*>(&h0);
        u.y = *reinterpret_cast<uint32_t*>(&h1);
        ((uint2*)g_xh)[i] = u;
    }
}

// ---------------- k_prep: build B hi/lo + bias smem image in global ----------
// image layout (byte offsets): [0,512) bias fp32; [512,..) Bhi [n][264] bf16;
// then Blo at +67584. Bs[n][k] = Bmat[k][n], Bmat = [W ; root].
__global__ void k_prep(const float* __restrict__ w, const float* __restrict__ root,
                       const float* __restrict__ bias) {
    int idx = blockIdx.x * 256 + threadIdx.x;
    char* img = (char*)g_bimg;
    if (idx < 256 * 128) {
        int k = idx >> 7, n = idx & 127;
        float v = (k < 128) ? w[(k << 7) + n] : root[((k - 128) << 7) + n];
        __nv_bfloat16 h = __float2bfloat16(v);
        float rl = v - __bfloat162float(h);
        *(__nv_bfloat16*)(img + 512 + (n * 264 + k) * 2) = h;
        *(__nv_bfloat16*)(img + 512 + 67584 + (n * 264 + k) * 2) =
            __float2bfloat16(rl);
    }
    if (blockIdx.x == 0 && threadIdx.x < 128)
        ((float*)img)[threadIdx.x] = bias[threadIdx.x];
}

// ---------------- k1: histogram (int4-vectorized; edge_index is int32) -------
__global__ void k_hist4(const int* __restrict__ ei) {
    int t = blockIdx.x * blockDim.x + threadIdx.x;
    if (t < N_EDGES / 4) {
        int4 r = ((const int4*)ei)[t];
        atomicAdd(&g_off[r.x], 1);
        atomicAdd(&g_off[r.y], 1);
        atomicAdd(&g_off[r.z], 1);
        atomicAdd(&g_off[r.w], 1);
    }
}

// ---------------- multi-block exclusive scan ---------------------------------
__global__ void k_scan_a() {
    __shared__ int ws[32];
    int tid = threadIdx.x, lane = tid & 31, wid = tid >> 5;
    int i = blockIdx.x * 1024 + tid;
    int v = (i < N_NODES) ? g_off[i] : 0;
    #pragma unroll
    for (int o = 16; o > 0; o >>= 1) v += __shfl_down_sync(0xffffffffu, v, o);
    if (lane == 0) ws[wid] = v;
    __syncthreads();
    if (wid == 0) {
        int t = ws[lane];
        #pragma unroll
        for (int o = 16; o > 0; o >>= 1) t += __shfl_down_sync(0xffffffffu, t, o);
        if (lane == 0) g_part[blockIdx.x] = t;
    }
}
__global__ void k_scan_b() {
    __shared__ int ws[4];
    int tid = threadIdx.x, lane = tid & 31, wid = tid >> 5;
    int v = (tid < SCAN_NB) ? g_part[tid] : 0;
    int xs = v;
    #pragma unroll
    for (int o = 1; o < 32; o <<= 1) {
        int t = __shfl_up_sync(0xffffffffu, xs, o);
        if (lane >= o) xs += t;
    }
    if (lane == 31) ws[wid] = xs;
    __syncthreads();
    if (tid == 0) {
        int a = 0;
        #pragma unroll
        for (int j = 0; j < 4; j++) { int t = ws[j]; ws[j] = a; a += t; }
        g_off[N_NODES] = a;
    }
    __syncthreads();
    int excl = ws[wid] + xs - v;
    if (tid < SCAN_NB) g_part[tid] = excl;
}
__global__ void k_scan_c() {
    __shared__ int ws[32];
    int tid = threadIdx.x, lane = tid & 31, wid = tid >> 5;
    int i = blockIdx.x * 1024 + tid;
    int v = (i < N_NODES) ? g_off[i] : 0;
    int xs = v;
    #pragma unroll
    for (int o = 1; o < 32; o <<= 1) {
        int t = __shfl_up_sync(0xffffffffu, xs, o);
        if (lane >= o) xs += t;
    }
    if (lane == 31) ws[wid] = xs;
    __syncthreads();
    if (wid == 0) {
        int t = ws[lane];
        #pragma unroll
        for (int o = 1; o < 32; o <<= 1) {
            int u = __shfl_up_sync(0xffffffffu, t, o);
            if (lane >= o) t += u;
        }
        ws[lane] = t;
    }
    __syncthreads();
    int excl = g_part[blockIdx.x] + ((wid == 0) ? 0 : ws[wid - 1]) + xs - v;
    if (i < N_NODES) { g_off[i] = excl; g_cursor[i] = excl; }
}

// ---------------- k3: bucket source cols (int4-vectorized) -------------------
__global__ void k_scatter4(const int* __restrict__ ei) {
    int t = blockIdx.x * blockDim.x + threadIdx.x;
    if (t < N_EDGES / 4) {
        int4 r = ((const int4*)ei)[t];
        int4 c = ((const int4*)(ei + N_EDGES))[t];
        int p0 = atomicAdd(&g_cursor[r.x], 1);
        int p1 = atomicAdd(&g_cursor[r.y], 1);
        int p2 = atomicAdd(&g_cursor[r.z], 1);
        int p3 = atomicAdd(&g_cursor[r.w], 1);
        g_scol[p0] = c.x; g_scol[p1] = c.y;
        g_scol[p2] = c.z; g_scol[p3] = c.w;
    }
}

// ---------------- k4: per-node fp16 gather-reduce + degree normalize ---------
// One warp per node; each lane owns 4 columns (uint2 = 4 halves per edge).
__global__ void k_agg(const float* __restrict__ x) {
    int gw = (blockIdx.x * blockDim.x + threadIdx.x) >> 5;
    int lane = threadIdx.x & 31;
    if (gw >= N_NODES) return;
    int s = g_off[gw], e = g_off[gw + 1];
    const uint2* xs = (const uint2*)g_xh;    // index: node*32 + lane
    float4 a0 = make_float4(0.f, 0.f, 0.f, 0.f);
    float4 a1 = make_float4(0.f, 0.f, 0.f, 0.f);
    int j = s;
    for (; j + 1 < e; j += 2) {              // 2-way MLP
        int c0 = g_scol[j], c1 = g_scol[j + 1];
        uint2 u0 = xs[(size_t)c0 * 32 + lane];
        uint2 u1 = xs[(size_t)c1 * 32 + lane];
        float2 f;
        f = __half22float2(*reinterpret_cast<__half2*>(&u0.x));
        a0.x += f.x; a0.y += f.y;
        f = __half22float2(*reinterpret_cast<__half2*>(&u0.y));
        a0.z += f.x; a0.w += f.y;
        f = __half22float2(*reinterpret_cast<__half2*>(&u1.x));
        a1.x += f.x; a1.y += f.y;
        f = __half22float2(*reinterpret_cast<__half2*>(&u1.y));
        a1.z += f.x; a1.w += f.y;
    }
    if (j < e) {
        int c0 = g_scol[j];
        uint2 u0 = xs[(size_t)c0 * 32 + lane];
        float2 f;
        f = __half22float2(*reinterpret_cast<__half2*>(&u0.x));
        a0.x += f.x; a0.y += f.y;
        f = __half22float2(*reinterpret_cast<__half2*>(&u0.y));
        a0.z += f.x; a0.w += f.y;
    }
    float inv = 1.0f / fmaxf((float)(e - s), 1.0f);
    float4 r;
    r.x = (a0.x + a1.x) * inv; r.y = (a0.y + a1.y) * inv;
    r.z = (a0.z + a1.z) * inv; r.w = (a0.w + a1.w) * inv;
    *(float4*)(g_agg + (size_t)gw * D + lane * 4) = r;
    (void)x;
}

// ---------------- k5: mma.sync bf16 split GEMM  out = [agg|x]@[W;root]+bias --
// B/bias copied from prebuilt global image. A staged per 64-K chunk,
// [row][k] bf16 (hi/lo), stride 72 elems. 8 warps in 2(M)x4(N).
#define BS_STRIDE 264
#define AS_STRIDE 72
#define SO_BIAS 0
#define SO_BHI  512
#define SO_BLO  (SO_BHI + 128 * BS_STRIDE * 2)          /* 68096 */
#define SO_AHI  (SO_BLO + 128 * BS_STRIDE * 2)          /* 135680 */
#define SO_ALO  (SO_AHI + 64 * AS_STRIDE * 2)
#define SMEM_GEMM (SO_ALO + 64 * AS_STRIDE * 2)
#define BIMG_U4 (SO_AHI / 16)                           /* 8480 */

__global__ void __launch_bounds__(256, 1) k_gemm_mma(
    const float* __restrict__ x, float* __restrict__ out) {
    extern __shared__ char smem[];
    uint32_t sb = smem_u32(smem);
    float* sBias = (float*)(smem + SO_BIAS);
    int tid = threadIdx.x, lane = tid & 31, wid = tid >> 5;

    // ---- copy prebuilt bias+Bhi+Blo image into smem -------------------------
    for (int i = tid; i < BIMG_U4; i += 256)
        ((uint4*)smem)[i] = g_bimg[i];
    __syncthreads();

    const int g = lane >> 2, tg = lane & 3;
    const int wm = wid >> 2, wn = wid & 3;       // 2 x 4 warp grid
    const int mbase_w = wm * 32, nbase_w = wn * 32;

    const uint32_t aAddrBase =
        sb + SO_AHI + (uint32_t)(mbase_w + (lane & 15)) * (AS_STRIDE * 2) +
        (uint32_t)(lane >> 4) * 16;
    const uint32_t bAddrBase =
        sb + SO_BHI + (uint32_t)(nbase_w + (lane & 7)) * (BS_STRIDE * 2) +
        (uint32_t)((lane >> 3) & 1) * 16;
    const uint32_t ALO_OFF = SO_ALO - SO_AHI;
    const uint32_t BLO_OFF = SO_BLO - SO_BHI;

    const int srow = tid >> 2, sq = tid & 3;

    for (int tile = blockIdx.x; tile < NT64; tile += gridDim.x) {
        int rb = tile * 64;
        float acc[2][4][4];
        #pragma unroll
        for (int mt = 0; mt < 2; mt++)
            #pragma unroll
            for (int nt = 0; nt < 4; nt++)
                #pragma unroll
                for (int q = 0; q < 4; q++) acc[mt][nt][q] = 0.f;

        #pragma unroll 1
        for (int kc = 0; kc < 4; kc++) {
            {   // stage A chunk: rows rb..rb+63, k cols kc*64..+63
                int gr = rb + srow;
                bool valid = gr < N_NODES;
                const float* src = (kc < 2)
                    ? (g_agg + (size_t)gr * D + kc * 64)
                    : (x + (size_t)gr * D + (kc - 2) * 64);
                #pragma unroll
                for (int p = 0; p < 4; p++) {
                    int col = (sq + p * 4) * 4;          // 0..60, step 16
                    float4 v = valid ? *(const float4*)(src + col)
                                     : make_float4(0.f, 0.f, 0.f, 0.f);
                    uint32_t h0 = packbf(v.x, v.y);
                    uint32_t h1 = packbf(v.z, v.w);
                    float r0 = v.x - __uint_as_float(h0 << 16);
                    float r1 = v.y - __uint_as_float(h0 & 0xffff0000u);
                    float r2 = v.z - __uint_as_float(h1 << 16);
                    float r3 = v.w - __uint_as_float(h1 & 0xffff0000u);
                    uint32_t l0 = packbf(r0, r1);
                    uint32_t l1 = packbf(r2, r3);
                    char* base = smem + (srow * AS_STRIDE + col) * 2;
                    *(uint2*)(base + SO_AHI) = make_uint2(h0, h1);
                    *(uint2*)(base + SO_ALO) = make_uint2(l0, l1);
                }
            }
            __syncthreads();

            #pragma unroll
            for (int k16 = 0; k16 < 4; k16++) {
                uint32_t bh[4][2], bl[4][2];
                uint32_t bcol = (uint32_t)(kc * 64 + k16 * 16) * 2;
                #pragma unroll
                for (int nt = 0; nt < 4; nt++) {
                    uint32_t ba = bAddrBase + (uint32_t)nt * (8 * BS_STRIDE * 2) + bcol;
                    LDSM_X2(bh[nt], ba);
                    LDSM_X2(bl[nt], ba + BLO_OFF);
                }
                #pragma unroll
                for (int mt = 0; mt < 2; mt++) {
                    uint32_t ah[4], al[4];
                    uint32_t aa = aAddrBase + (uint32_t)mt * (16 * AS_STRIDE * 2) +
                                  (uint32_t)k16 * 32;
                    LDSM_X4(ah, aa);
                    LDSM_X4(al, aa + ALO_OFF);
                    #pragma unroll
                    for (int nt = 0; nt < 4; nt++) {
                        MMA_BF16(acc[mt][nt], ah, bh[nt]);
                        MMA_BF16(acc[mt][nt], ah, bl[nt]);
                        MMA_BF16(acc[mt][nt], al, bh[nt]);
                    }
                }
            }
            __syncthreads();
        }

        // ---- epilogue: write 32x32 per warp with bias ----------------------
        #pragma unroll
        for (int mt = 0; mt < 2; mt++) {
            int r0 = rb + mbase_w + mt * 16 + g;
            #pragma unroll
            for (int nt = 0; nt < 4; nt++) {
                int col = nbase_w + nt * 8 + tg * 2;
                float b0 = sBias[col], b1 = sBias[col + 1];
                if (r0 < N_NODES)
                    *(float2*)(out + (size_t)r0 * D + col) =
                        make_float2(acc[mt][nt][0] + b0, acc[mt][nt][1] + b1);
                int r1 = r0 + 8;
                if (r1 < N_NODES)
                    *(float2*)(out + (size_t)r1 * D + col) =
                        make_float2(acc[mt][nt][2] + b0, acc[mt][nt][3] + b1);
            }
        }
    }
}

// ---------------- launch ------------------------------------------------------
extern "C" void kernel_launch(void* const* d_in, const int* in_sizes, int n_in,
                              void* d_out, int out_size) {
    const float* x    = (const float*)d_in[0];
    const int*   ei   = (const int*)d_in[1];     // int32 edge_index [2, E]
    const float* w    = (const float*)d_in[2];
    const float* root = (const float*)d_in[3];
    const float* bias = (const float*)d_in[4];
    float* out = (float*)d_out;

    (void)in_sizes; (void)n_in; (void)out_size;

    cudaFuncSetAttribute(k_gemm_mma, cudaFuncAttributeMaxDynamicSharedMemorySize,
                         SMEM_GEMM);

    k_zero<<<(N_NODES + 1 + 255) / 256, 256>>>();
    k_prep<<<128, 256>>>(w, root, bias);
    k_cvt<<<(N_NODES * 32 + 255) / 256, 256>>>(x);
    k_hist4<<<(N_EDGES / 4 + 255) / 256, 256>>>(ei);
    k_scan_a<<<SCAN_NB, 1024>>>();
    k_scan_b<<<1, 128>>>();
    k_scan_c<<<SCAN_NB, 1024>>>();
    k_scatter4<<<(N_EDGES / 4 + 255) / 256, 256>>>(ei);
    k_agg<<<(N_NODES * 32 + 255) / 256, 256>>>(x);
    k_gemm_mma<<<148, 256, SMEM_GEMM>>>(x, out);
}